// round 14
// baseline (speedup 1.0000x reference)
#include <cuda_runtime.h>
#include <cuda_bf16.h>
#include <math.h>

// Problem constants
#define NB   2048      // batch -> number of points
#define NT   128
#define NC   3
#define NJ   25
#define NE   64

#define GRID_BVK   128          // 4096 warps = 2048 points x 2 half-rows
#define THR_BVK    1024
#define ROUNDS     12           // >= ceil(log2(2048)) + safety

// smem: dm 128KB + comp 8KB + parent 8KB + deaths 8KB
#define SMEM_BVK   (32 * 1024 * 4 + NB * 4 * 3)

// Scratch in device globals (no runtime allocation allowed)
__device__ float    g_buf[NB * NJ];
__device__ float    Dm_buf[(size_t)NB * NB];       // 16 MB of SQUARED distances
__device__ float    blk_min[NB];                   // per-point min of g (race-free)
__device__ float    blk_max[NB];

// Boruvka cross-block state: per-round best-edge buffers + barrier.
// Barrier statics are replay-safe: bar_count returns to 0 after every full
// barrier cycle; bar_gen is monotone and only compared for equality.
__device__ unsigned long long best_r[ROUNDS][NB];
__device__ unsigned          bar_count = 0;
__device__ volatile unsigned bar_gen   = 0;

// ---------------------------------------------------------------------------
// Kernel 1: a[b,j] = mean_{t,c} x[b,t,c,j];  g[b,k] = sqrt(sum_j (a_j-a_k)^2)
// HBM-side: fully-coalesced float4 staging into smem (was 51% DRAM due to
// 25-lane strided LDG). Reduce phase reads smem (conflict-free strided).
// ---------------------------------------------------------------------------
__global__ void __launch_bounds__(256, 5)
k_reduce(const float* __restrict__ x) {
    __shared__ float xs[NT * NC * NJ];   // 9600 floats = 38.4 KB
    __shared__ float ap[8][NJ];
    __shared__ float a_s[NJ];

    const int b   = blockIdx.x;
    const int tid = threadIdx.x;

    // ---- coalesced staging: 2400 float4 per block ----
    {
        const float4* xb4 = (const float4*)(x + (size_t)b * (NT * NC * NJ));
        float4* xs4 = (float4*)xs;
        #pragma unroll 4
        for (int v = tid; v < (NT * NC * NJ) / 4; v += 256)
            xs4[v] = xb4[v];
    }
    __syncthreads();

    // ---- strided accumulation out of smem (bit-identical order to before) ----
    const int jj  = tid & 31;
    const int grp = tid >> 5;
    if (jj < NJ) {
        float s = 0.f;
        for (int r = grp; r < NT * NC; r += 8)
            s += xs[r * NJ + jj];
        ap[grp][jj] = s;
    }
    __syncthreads();

    if (tid < NJ) {
        float s = 0.f;
        #pragma unroll
        for (int g = 0; g < 8; ++g) s += ap[g][tid];
        a_s[tid] = s * (1.0f / (NT * NC));
    }
    __syncthreads();

    if (tid < 32) {
        float val = 0.f;
        if (tid < NJ) {
            float ak  = a_s[tid];
            float acc = 0.f;
            #pragma unroll
            for (int j = 0; j < NJ; ++j) {
                float d = a_s[j] - ak;
                acc = fmaf(d, d, acc);
            }
            val = sqrtf(acc);
            g_buf[b * NJ + tid] = val;
        }
        // g >= 0 so uint order == float order
        unsigned bmin = (tid < NJ) ? __float_as_uint(val) : 0x7f800000u;
        unsigned bmax = (tid < NJ) ? __float_as_uint(val) : 0u;
        unsigned wmin = __reduce_min_sync(0xffffffffu, bmin);
        unsigned wmax = __reduce_max_sync(0xffffffffu, bmax);
        if (tid == 0) {
            blk_min[b] = __uint_as_float(wmin);
            blk_max[b] = __uint_as_float(wmax);
        }
    }
}

// ---------------------------------------------------------------------------
// Kernel 2: Dm[i,k] = ||h_i - h_k||^2   (NO sqrt — deferred, monotone-safe).
// Each block redundantly reduces blk_min/blk_max for lo/hi.
// Tiled: grid (16,16), 256 threads, 128x128 tile, 8x8 outputs per thread.
// ---------------------------------------------------------------------------
__global__ void k_dist() {
    __shared__ float A[128][26];
    __shared__ float Bm[128][26];
    __shared__ unsigned mm_s[16];

    const int tid = threadIdx.x;
    const int r0  = blockIdx.y * 128;
    const int c0  = blockIdx.x * 128;

    // redundant min/max reduction (deterministic, no atomics)
    {
        unsigned lmin = 0x7f800000u, lmax = 0u;
        for (int v = tid; v < NB; v += 256) {
            lmin = min(lmin, __float_as_uint(blk_min[v]));
            lmax = max(lmax, __float_as_uint(blk_max[v]));
        }
        lmin = __reduce_min_sync(0xffffffffu, lmin);
        lmax = __reduce_max_sync(0xffffffffu, lmax);
        if ((tid & 31) == 0) {
            mm_s[tid >> 5]       = lmin;
            mm_s[8 + (tid >> 5)] = lmax;
        }
    }
    __syncthreads();
    unsigned u_lo = mm_s[0], u_hi = mm_s[8];
    #pragma unroll
    for (int k = 1; k < 8; ++k) {
        u_lo = min(u_lo, mm_s[k]);
        u_hi = max(u_hi, mm_s[8 + k]);
    }
    const float lo  = __uint_as_float(u_lo);
    const float hi  = __uint_as_float(u_hi);
    const float rng = hi - lo;
    const float inv = (rng > 1e-8f) ? (1.0f / rng) : 0.0f;

    for (int i = tid; i < 128 * NJ; i += 256) {
        int r = i / NJ, j = i - r * NJ;
        A[r][j]  = (g_buf[(r0 + r) * NJ + j] - lo) * inv;
        Bm[r][j] = (g_buf[(c0 + r) * NJ + j] - lo) * inv;
    }
    __syncthreads();

    const int tx = tid & 15;
    const int ty = tid >> 4;

    float acc[8][8];
    #pragma unroll
    for (int i = 0; i < 8; ++i)
        #pragma unroll
        for (int k = 0; k < 8; ++k) acc[i][k] = 0.f;

    #pragma unroll
    for (int j = 0; j < NJ; ++j) {
        float ra[8], rb[8];
        #pragma unroll
        for (int i = 0; i < 8; ++i) {
            ra[i] = A[ty + 16 * i][j];
            rb[i] = Bm[tx + 16 * i][j];
        }
        #pragma unroll
        for (int i = 0; i < 8; ++i)
            #pragma unroll
            for (int k = 0; k < 8; ++k) {
                float d = ra[i] - rb[k];
                acc[i][k] = fmaf(d, d, acc[i][k]);
            }
    }

    #pragma unroll
    for (int i = 0; i < 8; ++i) {
        int rr = r0 + ty + 16 * i;
        #pragma unroll
        for (int k = 0; k < 8; ++k) {
            int cc = c0 + tx + 16 * k;
            Dm_buf[(size_t)rr * NB + cc] = acc[i][k];   // squared distance
        }
    }
}

// ---------------------------------------------------------------------------
// Grid-wide sense-reversing barrier (all GRID_BVK blocks co-resident).
// ---------------------------------------------------------------------------
__device__ __forceinline__ void grid_barrier() {
    __syncthreads();
    if (threadIdx.x == 0) {
        __threadfence();
        unsigned gen = bar_gen;
        if (atomicAdd(&bar_count, 1u) == (unsigned)(gridDim.x - 1)) {
            bar_count = 0;
            __threadfence();
            bar_gen = gen + 1;
        } else {
            while (bar_gen == gen) { }
        }
        __threadfence();
    }
    __syncthreads();
}

// ---------------------------------------------------------------------------
// Kernel 3: persistent Boruvka on SQUARED distances (selection is monotone-
// invariant); sqrt applied only to selected deaths in the epilogue.
// Dm slices SMEM-resident; ONE grid barrier per round; hooking + flattening
// redundant per block in SMEM. Fused structure-layer epilogue.
// key = (d2_bits<<22) | (i<<11) | j   (d2 >= 0 so uint order == float order)
// ---------------------------------------------------------------------------
__global__ void __launch_bounds__(THR_BVK, 1)
k_boruvka(const float* __restrict__ centres,
          const float* __restrict__ sharp,
          float* __restrict__ out) {
    extern __shared__ char smem_raw[];
    float* dm_s     = (float*)smem_raw;                        // [32][1024]
    int*   comp_s   = (int*)(smem_raw + 32 * 1024 * 4);        // [2048]
    int*   parent_s = (int*)(smem_raw + 32 * 1024 * 4 + NB*4); // [2048]
    float* deaths_s = (float*)(smem_raw + 32 * 1024 * 4 + NB*8);// [2048] (d2)
    __shared__ int hooks_sh;

    const int tid  = threadIdx.x;
    const int lane = tid & 31;
    const int w    = tid >> 5;
    const int gw   = blockIdx.x * 32 + w;   // 0..4095
    const int i    = gw >> 1;               // point handled by this warp
    const int part = gw & 1;                // which half of the row
    const unsigned long long KMAX = 0xFFFFFFFFFFFFFFFFull;

    // ---- init: local state + this block's slice of best_r ----
    for (int v = tid; v < NB; v += THR_BVK) {
        comp_s[v]   = v;
        parent_s[v] = v;
        deaths_s[v] = -1.0f;
    }
    {
        unsigned long long* br = (unsigned long long*)best_r;
        const int per  = (ROUNDS * NB) / GRID_BVK;   // 192
        const int base = blockIdx.x * per;
        for (int v = tid; v < per; v += THR_BVK)
            br[base + v] = KMAX;
    }

    // one-time: stage this warp's Dm half-row into smem
    float4* dm4 = (float4*)(dm_s + w * 1024);
    {
        const float4* src = (const float4*)(Dm_buf + (size_t)i * NB + part * 1024);
        #pragma unroll
        for (int k = 0; k < 8; ++k)
            dm4[k * 32 + lane] = src[k * 32 + lane];
    }
    grid_barrier();   // best_r init visible everywhere

    const unsigned long long ibits = (unsigned long long)i << 11;
    const int jbase = part * 1024;
    int nc = NB;

    for (int r = 0; r < ROUNDS; ++r) {
        if (nc == 1) break;   // nc identical in all blocks -> uniform

        // ---- phase A: min cross-component edge, smem-resident scan ----
        const int ci = comp_s[i];
        unsigned long long best = KMAX;
        const int4* cp4 = (const int4*)comp_s;
        #pragma unroll
        for (int k = 0; k < 8; ++k) {
            const int v = k * 32 + lane;
            float4 w4 = dm4[v];
            int4   c4 = cp4[part * 256 + v];
            const int jb = jbase + v * 4;
            if (c4.x != ci) {
                unsigned long long key = ((unsigned long long)__float_as_uint(w4.x) << 22) | ibits | (jb + 0);
                if (key < best) best = key;
            }
            if (c4.y != ci) {
                unsigned long long key = ((unsigned long long)__float_as_uint(w4.y) << 22) | ibits | (jb + 1);
                if (key < best) best = key;
            }
            if (c4.z != ci) {
                unsigned long long key = ((unsigned long long)__float_as_uint(w4.z) << 22) | ibits | (jb + 2);
                if (key < best) best = key;
            }
            if (c4.w != ci) {
                unsigned long long key = ((unsigned long long)__float_as_uint(w4.w) << 22) | ibits | (jb + 3);
                if (key < best) best = key;
            }
        }
        #pragma unroll
        for (int off = 16; off; off >>= 1) {
            unsigned long long o = __shfl_down_sync(0xffffffffu, best, off);
            if (o < best) best = o;
        }
        if (lane == 0 && best != KMAX)
            atomicMin(&best_r[r][ci], best);

        if (tid == 0) hooks_sh = 0;
        grid_barrier();   // all atomicMin for round r complete

        // ---- phase B (block-local, redundant): hook roots ----
        for (int c = tid; c < NB; c += THR_BVK) {
            if (comp_s[c] == c) {
                unsigned long long b = best_r[r][c];
                if (b != KMAX) {
                    const int j  = (int)(b & 2047u);
                    const int rj = comp_s[j];
                    unsigned long long b2 = best_r[r][rj];
                    int back = (b2 != KMAX) ? comp_s[(int)(b2 & 2047u)] : -1;
                    const bool skip = (back == c) && (c > rj);
                    if (!skip) {
                        parent_s[c] = rj;
                        deaths_s[c] = __uint_as_float((unsigned)(b >> 22)); // d2
                        atomicAdd(&hooks_sh, 1);
                    }
                }
            }
        }
        __syncthreads();

        // ---- phase C (block-local): flatten labels ----
        for (int v = tid; v < NB; v += THR_BVK) {
            int p = comp_s[v];
            int q = parent_s[p];
            while (q != p) { p = q; q = parent_s[p]; }
            comp_s[v] = p;
        }
        nc -= hooks_sh;
        __syncthreads();
    }

    // ---- fused StructureElementLayer epilogue (sqrt only here) ----
    if (blockIdx.x < NE) {
        const int e  = blockIdx.x;
        const float cx = centres[2 * e],  cy = centres[2 * e + 1];
        const float sx = sharp[2 * e],    sy = sharp[2 * e + 1];
        const float t0  = sx * sx * cx * cx;
        const float s2y = sy * sy;

        float acc = 0.f;
        #pragma unroll
        for (int k = 0; k < 2; ++k) {
            float d2 = deaths_s[tid + k * THR_BVK];
            if (d2 >= 0.f) {
                float wdt = sqrtf(fmaxf(d2, 1e-12f));
                float dd  = wdt - cy;
                acc += expf(-(t0 + s2y * dd * dd));
            }
        }
        float* red = (float*)comp_s;
        red[tid] = acc;
        __syncthreads();
        #pragma unroll
        for (int s = 512; s; s >>= 1) {
            if (tid < s) red[tid] += red[tid + s];
            __syncthreads();
        }
        if (tid == 0) out[e] = red[0];
    }
}

// ---------------------------------------------------------------------------
extern "C" void kernel_launch(void* const* d_in, const int* in_sizes, int n_in,
                              void* d_out, int out_size) {
    const float* x       = (const float*)d_in[0];
    const float* centres = (const float*)d_in[1];
    const float* sharp   = (const float*)d_in[2];
    float*       out     = (float*)d_out;

    static int smem_set = 0;
    if (!smem_set) {
        cudaFuncSetAttribute(k_boruvka,
                             cudaFuncAttributeMaxDynamicSharedMemorySize,
                             SMEM_BVK);
        smem_set = 1;
    }

    k_reduce<<<NB, 256>>>(x);
    k_dist<<<dim3(16, 16), 256>>>();
    k_boruvka<<<GRID_BVK, THR_BVK, SMEM_BVK>>>(centres, sharp, out);
}

// round 15
// speedup vs baseline: 1.0437x; 1.0437x over previous
#include <cuda_runtime.h>
#include <cuda_bf16.h>
#include <math.h>

// Problem constants
#define NB   2048      // batch -> number of points
#define NT   128
#define NC   3
#define NJ   25
#define NE   64

#define GRID_BVK   128          // 4096 warps = 2048 points x 2 half-rows
#define THR_BVK    1024
#define ROUNDS     12           // >= ceil(log2(2048)) + safety

// smem: dm 128KB + comp 8KB + parent 8KB + deaths 8KB
#define SMEM_BVK   (32 * 1024 * 4 + NB * 4 * 3)

// Scratch in device globals (no runtime allocation allowed)
__device__ float    g_buf[NB * NJ];
__device__ float    Dm_buf[(size_t)NB * NB];       // 16 MB of SQUARED distances
__device__ float    blk_min[NB];                   // per-point min of g (race-free)
__device__ float    blk_max[NB];

// Boruvka cross-block state: per-round best-edge buffers + barrier.
__device__ unsigned long long best_r[ROUNDS][NB];
__device__ unsigned          bar_count = 0;
__device__ volatile unsigned bar_gen   = 0;

// ---------------------------------------------------------------------------
// Kernel 1: a[b,j] = mean_{t,c} x[b,t,c,j];  g[b,k] = sqrt(sum_j (a_j-a_k)^2)
// Residue-class streaming: 25 warps; warp w reads chunks c = w + 25t, so lane
// l's bin j = (32w + l) mod 25 is FIXED across its 12 chunks -> one register
// accumulator, fully-coalesced 128B requests, all 32 lanes active.
// (j, q) with q = (32w+l)/25 is a bijection over the 800 lanes -> unique,
// deterministic smem slot per lane; fixed-order final sums.
// ---------------------------------------------------------------------------
__global__ void __launch_bounds__(800, 2)
k_reduce(const float* __restrict__ x) {
    __shared__ float part[NJ][33];   // [j][q], padded
    __shared__ float a_s[NJ];

    const int b   = blockIdx.x;
    const int tid = threadIdx.x;
    const int w   = tid >> 5;        // 0..24
    const int l   = tid & 31;
    const float* xb = x + (size_t)b * (NT * NC * NJ);   // 9600 floats

    // ---- streaming accumulation: 12 coalesced chunks per warp ----
    float s = 0.f;
    #pragma unroll
    for (int t = 0; t < 12; ++t)
        s += xb[(w + 25 * t) * 32 + l];

    const int wl = 32 * w + l;       // 0..799
    const int j  = wl % 25;
    const int q  = wl / 25;          // 0..31
    part[j][q] = s;
    __syncthreads();

    if (tid < NJ) {
        float t = 0.f;
        #pragma unroll
        for (int k = 0; k < 32; ++k) t += part[tid][k];
        a_s[tid] = t * (1.0f / (NT * NC));
    }
    __syncthreads();

    if (tid < 32) {
        float val = 0.f;
        if (tid < NJ) {
            float ak  = a_s[tid];
            float acc = 0.f;
            #pragma unroll
            for (int jj = 0; jj < NJ; ++jj) {
                float d = a_s[jj] - ak;
                acc = fmaf(d, d, acc);
            }
            val = sqrtf(acc);
            g_buf[b * NJ + tid] = val;
        }
        // g >= 0 so uint order == float order
        unsigned bmin = (tid < NJ) ? __float_as_uint(val) : 0x7f800000u;
        unsigned bmax = (tid < NJ) ? __float_as_uint(val) : 0u;
        unsigned wmin = __reduce_min_sync(0xffffffffu, bmin);
        unsigned wmax = __reduce_max_sync(0xffffffffu, bmax);
        if (tid == 0) {
            blk_min[b] = __uint_as_float(wmin);
            blk_max[b] = __uint_as_float(wmax);
        }
    }
}

// ---------------------------------------------------------------------------
// Kernel 2: Dm[i,k] = ||h_i - h_k||^2   (NO sqrt — deferred, monotone-safe).
// ---------------------------------------------------------------------------
__global__ void k_dist() {
    __shared__ float A[128][26];
    __shared__ float Bm[128][26];
    __shared__ unsigned mm_s[16];

    const int tid = threadIdx.x;
    const int r0  = blockIdx.y * 128;
    const int c0  = blockIdx.x * 128;

    // redundant min/max reduction (deterministic, no atomics)
    {
        unsigned lmin = 0x7f800000u, lmax = 0u;
        for (int v = tid; v < NB; v += 256) {
            lmin = min(lmin, __float_as_uint(blk_min[v]));
            lmax = max(lmax, __float_as_uint(blk_max[v]));
        }
        lmin = __reduce_min_sync(0xffffffffu, lmin);
        lmax = __reduce_max_sync(0xffffffffu, lmax);
        if ((tid & 31) == 0) {
            mm_s[tid >> 5]       = lmin;
            mm_s[8 + (tid >> 5)] = lmax;
        }
    }
    __syncthreads();
    unsigned u_lo = mm_s[0], u_hi = mm_s[8];
    #pragma unroll
    for (int k = 1; k < 8; ++k) {
        u_lo = min(u_lo, mm_s[k]);
        u_hi = max(u_hi, mm_s[8 + k]);
    }
    const float lo  = __uint_as_float(u_lo);
    const float hi  = __uint_as_float(u_hi);
    const float rng = hi - lo;
    const float inv = (rng > 1e-8f) ? (1.0f / rng) : 0.0f;

    for (int i = tid; i < 128 * NJ; i += 256) {
        int r = i / NJ, j = i - r * NJ;
        A[r][j]  = (g_buf[(r0 + r) * NJ + j] - lo) * inv;
        Bm[r][j] = (g_buf[(c0 + r) * NJ + j] - lo) * inv;
    }
    __syncthreads();

    const int tx = tid & 15;
    const int ty = tid >> 4;

    float acc[8][8];
    #pragma unroll
    for (int i = 0; i < 8; ++i)
        #pragma unroll
        for (int k = 0; k < 8; ++k) acc[i][k] = 0.f;

    #pragma unroll
    for (int j = 0; j < NJ; ++j) {
        float ra[8], rb[8];
        #pragma unroll
        for (int i = 0; i < 8; ++i) {
            ra[i] = A[ty + 16 * i][j];
            rb[i] = Bm[tx + 16 * i][j];
        }
        #pragma unroll
        for (int i = 0; i < 8; ++i)
            #pragma unroll
            for (int k = 0; k < 8; ++k) {
                float d = ra[i] - rb[k];
                acc[i][k] = fmaf(d, d, acc[i][k]);
            }
    }

    #pragma unroll
    for (int i = 0; i < 8; ++i) {
        int rr = r0 + ty + 16 * i;
        #pragma unroll
        for (int k = 0; k < 8; ++k) {
            int cc = c0 + tx + 16 * k;
            Dm_buf[(size_t)rr * NB + cc] = acc[i][k];   // squared distance
        }
    }
}

// ---------------------------------------------------------------------------
// Grid-wide sense-reversing barrier (all GRID_BVK blocks co-resident).
// ---------------------------------------------------------------------------
__device__ __forceinline__ void grid_barrier() {
    __syncthreads();
    if (threadIdx.x == 0) {
        __threadfence();
        unsigned gen = bar_gen;
        if (atomicAdd(&bar_count, 1u) == (unsigned)(gridDim.x - 1)) {
            bar_count = 0;
            __threadfence();
            bar_gen = gen + 1;
        } else {
            while (bar_gen == gen) { }
        }
        __threadfence();
    }
    __syncthreads();
}

// ---------------------------------------------------------------------------
// Kernel 3: persistent Boruvka on SQUARED distances; sqrt only on selected
// deaths in the epilogue. Dm slices SMEM-resident; ONE grid barrier/round;
// hooking + flattening redundant per block in SMEM. Fused structure layer.
// key = (d2_bits<<22) | (i<<11) | j
// ---------------------------------------------------------------------------
__global__ void __launch_bounds__(THR_BVK, 1)
k_boruvka(const float* __restrict__ centres,
          const float* __restrict__ sharp,
          float* __restrict__ out) {
    extern __shared__ char smem_raw[];
    float* dm_s     = (float*)smem_raw;                         // [32][1024]
    int*   comp_s   = (int*)(smem_raw + 32 * 1024 * 4);         // [2048]
    int*   parent_s = (int*)(smem_raw + 32 * 1024 * 4 + NB*4);  // [2048]
    float* deaths_s = (float*)(smem_raw + 32 * 1024 * 4 + NB*8);// [2048] (d2)
    __shared__ int hooks_sh;

    const int tid  = threadIdx.x;
    const int lane = tid & 31;
    const int w    = tid >> 5;
    const int gw   = blockIdx.x * 32 + w;   // 0..4095
    const int i    = gw >> 1;               // point handled by this warp
    const int part = gw & 1;                // which half of the row
    const unsigned long long KMAX = 0xFFFFFFFFFFFFFFFFull;

    for (int v = tid; v < NB; v += THR_BVK) {
        comp_s[v]   = v;
        parent_s[v] = v;
        deaths_s[v] = -1.0f;
    }
    {
        unsigned long long* br = (unsigned long long*)best_r;
        const int per  = (ROUNDS * NB) / GRID_BVK;   // 192
        const int base = blockIdx.x * per;
        for (int v = tid; v < per; v += THR_BVK)
            br[base + v] = KMAX;
    }

    float4* dm4 = (float4*)(dm_s + w * 1024);
    {
        const float4* src = (const float4*)(Dm_buf + (size_t)i * NB + part * 1024);
        #pragma unroll
        for (int k = 0; k < 8; ++k)
            dm4[k * 32 + lane] = src[k * 32 + lane];
    }
    grid_barrier();   // best_r init visible everywhere

    const unsigned long long ibits = (unsigned long long)i << 11;
    const int jbase = part * 1024;
    int nc = NB;

    for (int r = 0; r < ROUNDS; ++r) {
        if (nc == 1) break;

        // ---- phase A: min cross-component edge, smem-resident scan ----
        const int ci = comp_s[i];
        unsigned long long best = KMAX;
        const int4* cp4 = (const int4*)comp_s;
        #pragma unroll
        for (int k = 0; k < 8; ++k) {
            const int v = k * 32 + lane;
            float4 w4 = dm4[v];
            int4   c4 = cp4[part * 256 + v];
            const int jb = jbase + v * 4;
            if (c4.x != ci) {
                unsigned long long key = ((unsigned long long)__float_as_uint(w4.x) << 22) | ibits | (jb + 0);
                if (key < best) best = key;
            }
            if (c4.y != ci) {
                unsigned long long key = ((unsigned long long)__float_as_uint(w4.y) << 22) | ibits | (jb + 1);
                if (key < best) best = key;
            }
            if (c4.z != ci) {
                unsigned long long key = ((unsigned long long)__float_as_uint(w4.z) << 22) | ibits | (jb + 2);
                if (key < best) best = key;
            }
            if (c4.w != ci) {
                unsigned long long key = ((unsigned long long)__float_as_uint(w4.w) << 22) | ibits | (jb + 3);
                if (key < best) best = key;
            }
        }
        #pragma unroll
        for (int off = 16; off; off >>= 1) {
            unsigned long long o = __shfl_down_sync(0xffffffffu, best, off);
            if (o < best) best = o;
        }
        if (lane == 0 && best != KMAX)
            atomicMin(&best_r[r][ci], best);

        if (tid == 0) hooks_sh = 0;
        grid_barrier();   // all atomicMin for round r complete

        // ---- phase B (block-local, redundant): hook roots ----
        for (int c = tid; c < NB; c += THR_BVK) {
            if (comp_s[c] == c) {
                unsigned long long b = best_r[r][c];
                if (b != KMAX) {
                    const int j  = (int)(b & 2047u);
                    const int rj = comp_s[j];
                    unsigned long long b2 = best_r[r][rj];
                    int back = (b2 != KMAX) ? comp_s[(int)(b2 & 2047u)] : -1;
                    const bool skip = (back == c) && (c > rj);
                    if (!skip) {
                        parent_s[c] = rj;
                        deaths_s[c] = __uint_as_float((unsigned)(b >> 22)); // d2
                        atomicAdd(&hooks_sh, 1);
                    }
                }
            }
        }
        __syncthreads();

        // ---- phase C (block-local): flatten labels ----
        for (int v = tid; v < NB; v += THR_BVK) {
            int p = comp_s[v];
            int q = parent_s[p];
            while (q != p) { p = q; q = parent_s[p]; }
            comp_s[v] = p;
        }
        nc -= hooks_sh;
        __syncthreads();
    }

    // ---- fused StructureElementLayer epilogue (sqrt only here) ----
    if (blockIdx.x < NE) {
        const int e  = blockIdx.x;
        const float cx = centres[2 * e],  cy = centres[2 * e + 1];
        const float sx = sharp[2 * e],    sy = sharp[2 * e + 1];
        const float t0  = sx * sx * cx * cx;
        const float s2y = sy * sy;

        float acc = 0.f;
        #pragma unroll
        for (int k = 0; k < 2; ++k) {
            float d2 = deaths_s[tid + k * THR_BVK];
            if (d2 >= 0.f) {
                float wdt = sqrtf(fmaxf(d2, 1e-12f));
                float dd  = wdt - cy;
                acc += expf(-(t0 + s2y * dd * dd));
            }
        }
        float* red = (float*)comp_s;
        red[tid] = acc;
        __syncthreads();
        #pragma unroll
        for (int s = 512; s; s >>= 1) {
            if (tid < s) red[tid] += red[tid + s];
            __syncthreads();
        }
        if (tid == 0) out[e] = red[0];
    }
}

// ---------------------------------------------------------------------------
extern "C" void kernel_launch(void* const* d_in, const int* in_sizes, int n_in,
                              void* d_out, int out_size) {
    const float* x       = (const float*)d_in[0];
    const float* centres = (const float*)d_in[1];
    const float* sharp   = (const float*)d_in[2];
    float*       out     = (float*)d_out;

    static int smem_set = 0;
    if (!smem_set) {
        cudaFuncSetAttribute(k_boruvka,
                             cudaFuncAttributeMaxDynamicSharedMemorySize,
                             SMEM_BVK);
        smem_set = 1;
    }

    k_reduce<<<NB, 800>>>(x);
    k_dist<<<dim3(16, 16), 256>>>();
    k_boruvka<<<GRID_BVK, THR_BVK, SMEM_BVK>>>(centres, sharp, out);
}